// round 14
// baseline (speedup 1.0000x reference)
#include <cuda_runtime.h>
#include <cstdint>

// Problem constants
#define BB 8
#define TT 32
#define CC 4880
#define DD 64
#define HH 64
#define AA 256
#define NG 256        // 4*H gate width
#define DIN 128       // 2*D
#define CSPLIT 8

// ---------------- scratch (device globals; no allocation) ----------------
__device__ float g_Spart[CSPLIT][TT][BB][DD];   // partial code sums
__device__ float g_CntPart[CSPLIT][TT][BB];     // partial nonzero counts
__device__ float g_Z[2][BB][TT][NG];            // input projections (dir, b, t, gate)
__device__ float g_lstm_out[BB * TT * 2 * HH];  // [b][t][128]
__device__ float g_epart[8][BB * TT];           // attention logit partials

// ---------------- math helpers ----------------
__device__ __forceinline__ float sigf(float x) {
    return 1.0f / (1.0f + __expf(-x));
}
__device__ __forceinline__ float tanhf_fast(float x) {
    return 1.0f - 2.0f / (__expf(2.0f * x) + 1.0f);
}

// =========================================================================
// K1: partial sums S[b,t,d] = sum_c x[b,t,c] * emb[c,d]  + count partials
// grid (16 t-pairs, 8 split), 256 threads. Each block handles TWO
// timesteps so each emb group load is reused 2x (halves emb L2 traffic)
// and 16 independent x-loads per group raise MLP.
// =========================================================================
__global__ void __launch_bounds__(256) k1_codes(const float* __restrict__ x,
                                                const float* __restrict__ emb) {
    const int t0 = blockIdx.x * 2, split = blockIdx.y;
    const int w = threadIdx.x >> 5, lane = threadIdx.x & 31;
    const int d0 = lane * 2;

    float acc[2][BB][2];
    float csum[2][BB];
#pragma unroll
    for (int tt = 0; tt < 2; tt++)
#pragma unroll
        for (int b = 0; b < BB; b++) {
            acc[tt][b][0] = 0.f; acc[tt][b][1] = 0.f; csum[tt][b] = 0.f;
        }

    for (int gi = split; gi * 32 < CC; gi += CSPLIT) {
        const int c0 = gi * 32 + w * 4;
        if (c0 < CC) {
            float2 e2[4];
#pragma unroll
            for (int ccx = 0; ccx < 4; ccx++)
                e2[ccx] = *(const float2*)&emb[(c0 + ccx) * DD + d0];
#pragma unroll
            for (int tt = 0; tt < 2; tt++) {
#pragma unroll
                for (int b = 0; b < BB; b++) {
                    const float4 xv = *(const float4*)&x[(size_t)(b * TT + t0 + tt) * CC + c0];
                    acc[tt][b][0] += xv.x * e2[0].x + xv.y * e2[1].x + xv.z * e2[2].x + xv.w * e2[3].x;
                    acc[tt][b][1] += xv.x * e2[0].y + xv.y * e2[1].y + xv.z * e2[2].y + xv.w * e2[3].y;
                    csum[tt][b] += (xv.x + xv.y) + (xv.z + xv.w);
                }
            }
        }
    }

    __shared__ float2 wp[8][2][BB][DD / 2];    // 8KB
    __shared__ float cw[8][2][BB];
#pragma unroll
    for (int tt = 0; tt < 2; tt++)
#pragma unroll
        for (int b = 0; b < BB; b++)
            wp[w][tt][b][lane] = make_float2(acc[tt][b][0], acc[tt][b][1]);
    if (lane == 0) {
#pragma unroll
        for (int tt = 0; tt < 2; tt++)
#pragma unroll
            for (int b = 0; b < BB; b++) cw[w][tt][b] = csum[tt][b];
    }
    __syncthreads();

    // 1024 outputs, 4 per thread
#pragma unroll
    for (int r = 0; r < 4; r++) {
        const int o = threadIdx.x + r * 256;
        const int tt = o >> 9, b = (o >> 6) & 7, d = o & 63;
        float s = 0.f;
#pragma unroll
        for (int ww = 0; ww < 8; ww++) {
            const float2 v = wp[ww][tt][b][d >> 1];
            s += (d & 1) ? v.y : v.x;
        }
        g_Spart[split][t0 + tt][b][d] = s;
    }
    if (threadIdx.x < 2 * BB) {
        const int tt = threadIdx.x >> 3, b = threadIdx.x & 7;
        float s = 0.f;
#pragma unroll
        for (int ww = 0; ww < 8; ww++) s += cw[ww][tt][b];
        g_CntPart[split][t0 + tt][b] = s;
    }
}

// =========================================================================
// K2: per (t, dir): counts, avg_xt, avg_ht, z projection.
// grid (32 t, 2 dir), 256 threads. Each block streams only its dir's Wih
// (64KB) in 16 double-buffered chunks; 64 blocks double SM coverage vs
// the old 32-block shape.
// =========================================================================
__global__ void __launch_bounds__(256) k2_prep(const float* __restrict__ Wg,
                                               const float* __restrict__ bg,
                                               const float* __restrict__ Wih_f,
                                               const float* __restrict__ b_f,
                                               const float* __restrict__ Wih_b,
                                               const float* __restrict__ b_b) {
    const int t = blockIdx.x, dir = blockIdx.y;
    const int tid = threadIdx.x;
    __shared__ float rows[BB][DIN];         // 4KB
    __shared__ float4 wbuf2[2][512];        // 16KB: [slot][8 k-rows x 64 quads]
    __shared__ float cnt_sm[BB], has_sm[BB];

    // ---- stage Wg into wbuf2 (1024 float4, 4 each) ----
    {
        const float4* src = (const float4*)Wg;
        float4* dst = (float4*)wbuf2;
#pragma unroll
        for (int i = 0; i < 4; i++) dst[tid + i * 256] = src[tid + i * 256];
    }
    // ---- counts from partials ----
    if (tid < BB) {
        float s = 0.f;
#pragma unroll
        for (int sp = 0; sp < CSPLIT; sp++) s += g_CntPart[sp][t][tid];
        cnt_sm[tid] = fmaxf(s, 1.f);
        has_sm[tid] = (s > 0.f) ? 1.f : 0.f;
    }
    __syncthreads();

    // ---- avg_xt: 512 outputs, 2 per thread ----
#pragma unroll
    for (int r = 0; r < 2; r++) {
        const int o = tid + r * 256;
        const int b = o >> 6, d = o & 63;
        float s = 0.f;
#pragma unroll
        for (int sp = 0; sp < CSPLIT; sp++) s += g_Spart[sp][t][b][d];
        rows[b][DD + d] = s / cnt_sm[b];
    }
    __syncthreads();

    // ---- avg_ht = avg_xt @ Wg + bg*has : 2 outputs per thread ----
#pragma unroll
    for (int r = 0; r < 2; r++) {
        const int o = tid + r * 256;
        const int b = o >> 6, d = o & 63;
        const float* wg_sm = (const float*)wbuf2;
        float a = bg[d] * has_sm[b];
#pragma unroll 16
        for (int k = 0; k < DD; k++) a += rows[b][DD + k] * wg_sm[k * DD + d];
        rows[b][d] = a;
    }
    __syncthreads();

    // ---- z = lstm_in @ Wih + bias : double-buffered chunks ----
    const float* __restrict__ Wih  = dir ? Wih_b : Wih_f;
    const float* __restrict__ bias = dir ? b_b : b_f;
    const int q = tid & 63, bg2 = tid >> 6;   // gate quad, b-pair index
    const int b0 = bg2 * 2;
    const float4 bv = *(const float4*)&bias[q * 4];
    float acc0[4] = {bv.x, bv.y, bv.z, bv.w};
    float acc1[4] = {bv.x, bv.y, bv.z, bv.w};

    // preload chunk 0 (8 k-rows = 512 float4; 2 per thread)
    float4 ra = ((const float4*)Wih)[tid];
    float4 rb = ((const float4*)Wih)[tid + 256];
    {
        float4* ds = &wbuf2[0][0];
        ds[tid] = ra;
        ds[tid + 256] = rb;
    }
    __syncthreads();

    for (int ch = 0; ch < 16; ch++) {
        const int slot = ch & 1;
        if (ch < 15) {
            const float4* wsrc = (const float4*)&Wih[(ch + 1) * 8 * NG];
            ra = wsrc[tid];
            rb = wsrc[tid + 256];
        }
        const float4* cs = &wbuf2[slot][0];
#pragma unroll
        for (int kk = 0; kk < 8; kk++) {
            const float4 wv = cs[kk * 64 + q];
            const int k = ch * 8 + kk;
            const float r0 = rows[b0][k];
            const float r1 = rows[b0 + 1][k];
            acc0[0] += r0 * wv.x; acc0[1] += r0 * wv.y; acc0[2] += r0 * wv.z; acc0[3] += r0 * wv.w;
            acc1[0] += r1 * wv.x; acc1[1] += r1 * wv.y; acc1[2] += r1 * wv.z; acc1[3] += r1 * wv.w;
        }
        if (ch < 15) {
            float4* ds = &wbuf2[slot ^ 1][0];
            ds[tid] = ra;
            ds[tid + 256] = rb;
        }
        __syncthreads();
    }
    *(float4*)&g_Z[dir][b0][t][q * 4]     = make_float4(acc0[0], acc0[1], acc0[2], acc0[3]);
    *(float4*)&g_Z[dir][b0 + 1][t][q * 4] = make_float4(acc1[0], acc1[1], acc1[2], acc1[3]);
}

// =========================================================================
// K3: bidirectional LSTM, split by (dir, batch). grid=16, 256 threads.
// [R10 body]
// =========================================================================
__global__ void __launch_bounds__(256, 1) k3_lstm(const float* __restrict__ Whh_f,
                                                  const float* __restrict__ Whh_b) {
    const int dir = blockIdx.x >> 3;
    const int b = blockIdx.x & 7;
    const float* __restrict__ Whh = dir ? Whh_b : Whh_f;
    __shared__ float h_sm[HH];
    __shared__ float z_sm[NG];
    const int g = threadIdx.x;

    unsigned long long wpk[32];
#pragma unroll
    for (int i = 0; i < 32; i++) {
        const float w0 = Whh[(2 * i) * NG + g];
        const float w1 = Whh[(2 * i + 1) * NG + g];
        asm("mov.b64 %0, {%1, %2};" : "=l"(wpk[i]) : "f"(w0), "f"(w1));
    }
    if (g < HH) h_sm[g] = 0.f;
    float cst = 0.f;
    __syncthreads();

    const float* __restrict__ zrow = &g_Z[dir][b][0][0];
    float* __restrict__ orow = &g_lstm_out[b * TT * (2 * HH) + dir * HH];

    const int t0 = dir ? (TT - 1) : 0;
    float zcur = zrow[t0 * NG + g];

    for (int s = 0; s < TT; s++) {
        const int t = dir ? (TT - 1 - s) : s;
        float znext = 0.f;
        if (s + 1 < TT) {
            const int tn = dir ? (TT - 2 - s) : (s + 1);
            znext = zrow[tn * NG + g];
        }
        unsigned long long a0 = 0ull, a1 = 0ull, a2 = 0ull, a3 = 0ull;
        const ulonglong2* hp = (const ulonglong2*)h_sm;
#pragma unroll
        for (int i = 0; i < 16; i += 2) {
            const ulonglong2 h0 = hp[i];
            const ulonglong2 h1 = hp[i + 1];
            asm("fma.rn.f32x2 %0, %1, %2, %0;" : "+l"(a0) : "l"(wpk[2 * i]),     "l"(h0.x));
            asm("fma.rn.f32x2 %0, %1, %2, %0;" : "+l"(a1) : "l"(wpk[2 * i + 1]), "l"(h0.y));
            asm("fma.rn.f32x2 %0, %1, %2, %0;" : "+l"(a2) : "l"(wpk[2 * i + 2]), "l"(h1.x));
            asm("fma.rn.f32x2 %0, %1, %2, %0;" : "+l"(a3) : "l"(wpk[2 * i + 3]), "l"(h1.y));
        }
        float l0, h0f, l1, h1f, l2, h2f, l3, h3f;
        asm("mov.b64 {%0, %1}, %2;" : "=f"(l0), "=f"(h0f) : "l"(a0));
        asm("mov.b64 {%0, %1}, %2;" : "=f"(l1), "=f"(h1f) : "l"(a1));
        asm("mov.b64 {%0, %1}, %2;" : "=f"(l2), "=f"(h2f) : "l"(a2));
        asm("mov.b64 {%0, %1}, %2;" : "=f"(l3), "=f"(h3f) : "l"(a3));
        z_sm[g] = zcur + ((l0 + h0f) + (l1 + h1f)) + ((l2 + h2f) + (l3 + h3f));
        __syncthreads();

        if (g < HH) {
            const float ziv = z_sm[g];
            const float zfv = z_sm[64 + g];
            const float zgv = z_sm[128 + g];
            const float zov = z_sm[192 + g];
            const float ig = sigf(ziv), fg = sigf(zfv);
            const float gg = tanhf_fast(zgv), og = sigf(zov);
            cst = fg * cst + ig * gg;
            const float hnew = og * tanhf_fast(cst);
            h_sm[g] = hnew;
            orow[t * (2 * HH) + g] = hnew;
        }
        __syncthreads();
        zcur = znext;
    }
}

// =========================================================================
// K4: attention logit partials, column-split, finer row split.
// grid 128 = (8 col-groups cg) x (16 row-groups rg of 16 bt rows).
// [R13 body]
// =========================================================================
__global__ void __launch_bounds__(256) k4_attn(const float* __restrict__ Wa,
                                               const float* __restrict__ ba,
                                               const float* __restrict__ ua) {
    const int cg = blockIdx.x & 7;        // col group: cols cg*32..+31
    const int rg = blockIdx.x >> 3;       // row group: bt rows rg*16..+15
    const int tid = threadIdx.x;
    const int lane = tid & 31, w = tid >> 5;
    const int col = cg * 32 + lane;
    __shared__ float rows_sm[16][DIN];    // 8KB
    __shared__ float wa_sm[DIN][32];      // 16KB  [k][c]

    // stage 16 lstm_out rows: 512 float4 / 256 threads (2 each)
    {
        const float4* src = (const float4*)&g_lstm_out[rg * 16 * DIN];
        float4* dst = (float4*)rows_sm;
        dst[tid] = src[tid];
        dst[tid + 256] = src[tid + 256];
    }
    // stage Wa column slice [128][32]: 1024 float4 / 256 threads
    {
#pragma unroll
        for (int i = 0; i < 4; i++) {
            const int idx = tid + i * 256;      // float4 index
            const int k = idx >> 3, seg = idx & 7;
            *(float4*)&wa_sm[k][seg * 4] =
                *(const float4*)&Wa[k * AA + cg * 32 + seg * 4];
        }
    }
    __syncthreads();

    // warp w -> local rows w*2, w*2+1; lane -> col
    float acc0 = 0.f, acc1 = 0.f;
    const int r0 = w * 2;
#pragma unroll 4
    for (int kq = 0; kq < 32; kq++) {
        const float4 a0v = *(const float4*)&rows_sm[r0 + 0][kq * 4];
        const float4 a1v = *(const float4*)&rows_sm[r0 + 1][kq * 4];
        const float w0 = wa_sm[kq * 4 + 0][lane];
        const float w1 = wa_sm[kq * 4 + 1][lane];
        const float w2 = wa_sm[kq * 4 + 2][lane];
        const float w3 = wa_sm[kq * 4 + 3][lane];
        acc0 += a0v.x * w0 + a0v.y * w1 + a0v.z * w2 + a0v.w * w3;
        acc1 += a1v.x * w0 + a1v.y * w1 + a1v.z * w2 + a1v.w * w3;
    }
    const float bav = ba[col], uav = ua[col];
    float p0 = tanhf_fast(acc0 + bav) * uav;
    float p1 = tanhf_fast(acc1 + bav) * uav;
#pragma unroll
    for (int o = 16; o > 0; o >>= 1) {
        p0 += __shfl_down_sync(0xffffffffu, p0, o);
        p1 += __shfl_down_sync(0xffffffffu, p1, o);
    }
    if (lane == 0) {
        const int bt = rg * 16 + r0;
        g_epart[cg][bt + 0] = p0;
        g_epart[cg][bt + 1] = p1;
    }
}

// =========================================================================
// K5: sum logit partials, softmax over t, context, leaky_relu, head.
// grid 8 (b), 128 threads. [R13 body]
// =========================================================================
__global__ void __launch_bounds__(128) k5_head(const float* __restrict__ Wo,
                                               const float* __restrict__ bo,
                                               float* __restrict__ out) {
    const int b = blockIdx.x;
    const int tid = threadIdx.x;
    __shared__ float alpha[TT];
    __shared__ float red[128];

    if (tid < 32) {
        float e = 0.f;
#pragma unroll
        for (int cg = 0; cg < 8; cg++) e += g_epart[cg][b * TT + tid];
        float m = e;
#pragma unroll
        for (int o = 16; o > 0; o >>= 1) m = fmaxf(m, __shfl_xor_sync(0xffffffffu, m, o));
        float ex = __expf(e - m);
        float sum = ex;
#pragma unroll
        for (int o = 16; o > 0; o >>= 1) sum += __shfl_xor_sync(0xffffffffu, sum, o);
        alpha[tid] = ex / sum;
    }
    __syncthreads();

    float ctx = 0.f;
#pragma unroll 8
    for (int t = 0; t < TT; t++)
        ctx += alpha[t] * g_lstm_out[(b * TT + t) * DIN + tid];
    const float v = (ctx > 0.f) ? ctx : 0.5f * ctx;
    red[tid] = v * Wo[tid];
    __syncthreads();
#pragma unroll
    for (int s = 64; s > 0; s >>= 1) {
        if (tid < s) red[tid] += red[tid + s];
        __syncthreads();
    }
    if (tid == 0) out[b] = 1.f / (1.f + __expf(-(red[0] + bo[0])));
}

// =========================================================================
extern "C" void kernel_launch(void* const* d_in, const int* in_sizes, int n_in,
                              void* d_out, int out_size) {
    const float* x     = (const float*)d_in[0];
    // d_in[1] = visit_lens (int64) — unused by the reference math
    const float* emb   = (const float*)d_in[2];
    const float* Wg    = (const float*)d_in[3];
    const float* bg    = (const float*)d_in[4];
    const float* Wih_f = (const float*)d_in[5];
    const float* Whh_f = (const float*)d_in[6];
    const float* b_f   = (const float*)d_in[7];
    const float* Wih_b = (const float*)d_in[8];
    const float* Whh_b = (const float*)d_in[9];
    const float* b_b   = (const float*)d_in[10];
    const float* Wa    = (const float*)d_in[11];
    const float* ba    = (const float*)d_in[12];
    const float* ua    = (const float*)d_in[13];
    const float* Wo    = (const float*)d_in[14];
    const float* bo    = (const float*)d_in[15];
    float* out = (float*)d_out;

    k1_codes<<<dim3(TT / 2, CSPLIT), 256>>>(x, emb);
    k2_prep<<<dim3(TT, 2), 256>>>(Wg, bg, Wih_f, b_f, Wih_b, b_b);
    k3_lstm<<<16, 256>>>(Whh_f, Whh_b);
    k4_attn<<<128, 256>>>(Wa, ba, ua);
    k5_head<<<BB, 128>>>(Wo, bo, out);
}

// round 15
// speedup vs baseline: 1.4099x; 1.4099x over previous
#include <cuda_runtime.h>
#include <cstdint>

// Problem constants
#define BB 8
#define TT 32
#define CC 4880
#define DD 64
#define HH 64
#define AA 256
#define NG 256        // 4*H gate width
#define DIN 128       // 2*D
#define CSPLIT 8

// ---------------- scratch (device globals; no allocation) ----------------
__device__ float g_Spart[CSPLIT][TT][BB][DD];   // partial code sums
__device__ float g_CntPart[CSPLIT][TT][BB];     // partial nonzero counts
__device__ float g_Z[2][BB][TT][NG];            // input projections (dir, b, t, gate)
__device__ float g_lstm_out[BB * TT * 2 * HH];  // [b][t][128]
__device__ float g_epart[8][BB * TT];           // attention logit partials

// ---------------- math helpers ----------------
__device__ __forceinline__ float sigf(float x) {
    return 1.0f / (1.0f + __expf(-x));
}
__device__ __forceinline__ float tanhf_fast(float x) {
    return 1.0f - 2.0f / (__expf(2.0f * x) + 1.0f);
}

// =========================================================================
// K1: partial sums S[b,t,d] = sum_c x[b,t,c] * emb[c,d]  + count partials
// grid (32 t, 8 split), 256 threads (8 warps).  [R13 body — accumulators
// fit in registers; the R14 t-paired variant spilled and regressed 23us]
// =========================================================================
__global__ void __launch_bounds__(256) k1_codes(const float* __restrict__ x,
                                                const float* __restrict__ emb) {
    const int t = blockIdx.x, split = blockIdx.y;
    const int w = threadIdx.x >> 5, lane = threadIdx.x & 31;
    const int d0 = lane * 2;

    float acc[BB][2];
    float csum[BB];
#pragma unroll
    for (int b = 0; b < BB; b++) { acc[b][0] = 0.f; acc[b][1] = 0.f; csum[b] = 0.f; }

#pragma unroll 2
    for (int gi = split; gi * 32 < CC; gi += CSPLIT) {
        const int c0 = gi * 32 + w * 4;
        if (c0 < CC) {
            float2 e2[4];
#pragma unroll
            for (int ccx = 0; ccx < 4; ccx++)
                e2[ccx] = *(const float2*)&emb[(c0 + ccx) * DD + d0];
#pragma unroll
            for (int b = 0; b < BB; b++) {
                const float4 xv = *(const float4*)&x[(size_t)(b * TT + t) * CC + c0];
                acc[b][0] += xv.x * e2[0].x + xv.y * e2[1].x + xv.z * e2[2].x + xv.w * e2[3].x;
                acc[b][1] += xv.x * e2[0].y + xv.y * e2[1].y + xv.z * e2[2].y + xv.w * e2[3].y;
                csum[b] += (xv.x + xv.y) + (xv.z + xv.w);
            }
        }
    }

    __shared__ float2 wp[8][BB][DD / 2];
    __shared__ float cw[8][BB];
#pragma unroll
    for (int b = 0; b < BB; b++)
        wp[w][b][lane] = make_float2(acc[b][0], acc[b][1]);
    if (lane == 0) {
#pragma unroll
        for (int b = 0; b < BB; b++) cw[w][b] = csum[b];
    }
    __syncthreads();

    for (int o = threadIdx.x; o < BB * DD; o += 256) {
        const int b = o >> 6, d = o & 63;
        float s = 0.f;
#pragma unroll
        for (int ww = 0; ww < 8; ww++) {
            const float2 v = wp[ww][b][d >> 1];
            s += (d & 1) ? v.y : v.x;
        }
        g_Spart[split][t][b][d] = s;
    }
    if (threadIdx.x < BB) {
        float s = 0.f;
#pragma unroll
        for (int ww = 0; ww < 8; ww++) s += cw[ww][threadIdx.x];
        g_CntPart[split][t][threadIdx.x] = s;
    }
}

// =========================================================================
// K2: per (t, dir): counts, avg_xt, avg_ht, z projection.
// grid (32 t, 2 dir), 256 threads. [R14 body — kept for the A/B: each
// block streams only its dir's Wih (64KB) in 16 double-buffered chunks]
// =========================================================================
__global__ void __launch_bounds__(256) k2_prep(const float* __restrict__ Wg,
                                               const float* __restrict__ bg,
                                               const float* __restrict__ Wih_f,
                                               const float* __restrict__ b_f,
                                               const float* __restrict__ Wih_b,
                                               const float* __restrict__ b_b) {
    const int t = blockIdx.x, dir = blockIdx.y;
    const int tid = threadIdx.x;
    __shared__ float rows[BB][DIN];         // 4KB
    __shared__ float4 wbuf2[2][512];        // 16KB: [slot][8 k-rows x 64 quads]
    __shared__ float cnt_sm[BB], has_sm[BB];

    // ---- stage Wg into wbuf2 (1024 float4, 4 each) ----
    {
        const float4* src = (const float4*)Wg;
        float4* dst = (float4*)wbuf2;
#pragma unroll
        for (int i = 0; i < 4; i++) dst[tid + i * 256] = src[tid + i * 256];
    }
    // ---- counts from partials ----
    if (tid < BB) {
        float s = 0.f;
#pragma unroll
        for (int sp = 0; sp < CSPLIT; sp++) s += g_CntPart[sp][t][tid];
        cnt_sm[tid] = fmaxf(s, 1.f);
        has_sm[tid] = (s > 0.f) ? 1.f : 0.f;
    }
    __syncthreads();

    // ---- avg_xt: 512 outputs, 2 per thread ----
#pragma unroll
    for (int r = 0; r < 2; r++) {
        const int o = tid + r * 256;
        const int b = o >> 6, d = o & 63;
        float s = 0.f;
#pragma unroll
        for (int sp = 0; sp < CSPLIT; sp++) s += g_Spart[sp][t][b][d];
        rows[b][DD + d] = s / cnt_sm[b];
    }
    __syncthreads();

    // ---- avg_ht = avg_xt @ Wg + bg*has : 2 outputs per thread ----
#pragma unroll
    for (int r = 0; r < 2; r++) {
        const int o = tid + r * 256;
        const int b = o >> 6, d = o & 63;
        const float* wg_sm = (const float*)wbuf2;
        float a = bg[d] * has_sm[b];
#pragma unroll 16
        for (int k = 0; k < DD; k++) a += rows[b][DD + k] * wg_sm[k * DD + d];
        rows[b][d] = a;
    }
    __syncthreads();

    // ---- z = lstm_in @ Wih + bias : double-buffered chunks ----
    const float* __restrict__ Wih  = dir ? Wih_b : Wih_f;
    const float* __restrict__ bias = dir ? b_b : b_f;
    const int q = tid & 63, bg2 = tid >> 6;   // gate quad, b-pair index
    const int b0 = bg2 * 2;
    const float4 bv = *(const float4*)&bias[q * 4];
    float acc0[4] = {bv.x, bv.y, bv.z, bv.w};
    float acc1[4] = {bv.x, bv.y, bv.z, bv.w};

    // preload chunk 0 (8 k-rows = 512 float4; 2 per thread)
    float4 ra = ((const float4*)Wih)[tid];
    float4 rb = ((const float4*)Wih)[tid + 256];
    {
        float4* ds = &wbuf2[0][0];
        ds[tid] = ra;
        ds[tid + 256] = rb;
    }
    __syncthreads();

    for (int ch = 0; ch < 16; ch++) {
        const int slot = ch & 1;
        if (ch < 15) {
            const float4* wsrc = (const float4*)&Wih[(ch + 1) * 8 * NG];
            ra = wsrc[tid];
            rb = wsrc[tid + 256];
        }
        const float4* cs = &wbuf2[slot][0];
#pragma unroll
        for (int kk = 0; kk < 8; kk++) {
            const float4 wv = cs[kk * 64 + q];
            const int k = ch * 8 + kk;
            const float r0 = rows[b0][k];
            const float r1 = rows[b0 + 1][k];
            acc0[0] += r0 * wv.x; acc0[1] += r0 * wv.y; acc0[2] += r0 * wv.z; acc0[3] += r0 * wv.w;
            acc1[0] += r1 * wv.x; acc1[1] += r1 * wv.y; acc1[2] += r1 * wv.z; acc1[3] += r1 * wv.w;
        }
        if (ch < 15) {
            float4* ds = &wbuf2[slot ^ 1][0];
            ds[tid] = ra;
            ds[tid + 256] = rb;
        }
        __syncthreads();
    }
    *(float4*)&g_Z[dir][b0][t][q * 4]     = make_float4(acc0[0], acc0[1], acc0[2], acc0[3]);
    *(float4*)&g_Z[dir][b0 + 1][t][q * 4] = make_float4(acc1[0], acc1[1], acc1[2], acc1[3]);
}

// =========================================================================
// K3: bidirectional LSTM, split by (dir, batch). grid=16, 256 threads.
// [R10 body]
// =========================================================================
__global__ void __launch_bounds__(256, 1) k3_lstm(const float* __restrict__ Whh_f,
                                                  const float* __restrict__ Whh_b) {
    const int dir = blockIdx.x >> 3;
    const int b = blockIdx.x & 7;
    const float* __restrict__ Whh = dir ? Whh_b : Whh_f;
    __shared__ float h_sm[HH];
    __shared__ float z_sm[NG];
    const int g = threadIdx.x;

    unsigned long long wpk[32];
#pragma unroll
    for (int i = 0; i < 32; i++) {
        const float w0 = Whh[(2 * i) * NG + g];
        const float w1 = Whh[(2 * i + 1) * NG + g];
        asm("mov.b64 %0, {%1, %2};" : "=l"(wpk[i]) : "f"(w0), "f"(w1));
    }
    if (g < HH) h_sm[g] = 0.f;
    float cst = 0.f;
    __syncthreads();

    const float* __restrict__ zrow = &g_Z[dir][b][0][0];
    float* __restrict__ orow = &g_lstm_out[b * TT * (2 * HH) + dir * HH];

    const int t0 = dir ? (TT - 1) : 0;
    float zcur = zrow[t0 * NG + g];

    for (int s = 0; s < TT; s++) {
        const int t = dir ? (TT - 1 - s) : s;
        float znext = 0.f;
        if (s + 1 < TT) {
            const int tn = dir ? (TT - 2 - s) : (s + 1);
            znext = zrow[tn * NG + g];
        }
        unsigned long long a0 = 0ull, a1 = 0ull, a2 = 0ull, a3 = 0ull;
        const ulonglong2* hp = (const ulonglong2*)h_sm;
#pragma unroll
        for (int i = 0; i < 16; i += 2) {
            const ulonglong2 h0 = hp[i];
            const ulonglong2 h1 = hp[i + 1];
            asm("fma.rn.f32x2 %0, %1, %2, %0;" : "+l"(a0) : "l"(wpk[2 * i]),     "l"(h0.x));
            asm("fma.rn.f32x2 %0, %1, %2, %0;" : "+l"(a1) : "l"(wpk[2 * i + 1]), "l"(h0.y));
            asm("fma.rn.f32x2 %0, %1, %2, %0;" : "+l"(a2) : "l"(wpk[2 * i + 2]), "l"(h1.x));
            asm("fma.rn.f32x2 %0, %1, %2, %0;" : "+l"(a3) : "l"(wpk[2 * i + 3]), "l"(h1.y));
        }
        float l0, h0f, l1, h1f, l2, h2f, l3, h3f;
        asm("mov.b64 {%0, %1}, %2;" : "=f"(l0), "=f"(h0f) : "l"(a0));
        asm("mov.b64 {%0, %1}, %2;" : "=f"(l1), "=f"(h1f) : "l"(a1));
        asm("mov.b64 {%0, %1}, %2;" : "=f"(l2), "=f"(h2f) : "l"(a2));
        asm("mov.b64 {%0, %1}, %2;" : "=f"(l3), "=f"(h3f) : "l"(a3));
        z_sm[g] = zcur + ((l0 + h0f) + (l1 + h1f)) + ((l2 + h2f) + (l3 + h3f));
        __syncthreads();

        if (g < HH) {
            const float ziv = z_sm[g];
            const float zfv = z_sm[64 + g];
            const float zgv = z_sm[128 + g];
            const float zov = z_sm[192 + g];
            const float ig = sigf(ziv), fg = sigf(zfv);
            const float gg = tanhf_fast(zgv), og = sigf(zov);
            cst = fg * cst + ig * gg;
            const float hnew = og * tanhf_fast(cst);
            h_sm[g] = hnew;
            orow[t * (2 * HH) + g] = hnew;
        }
        __syncthreads();
        zcur = znext;
    }
}

// =========================================================================
// K4: attention logit partials, column-split, finer row split.
// grid 128 = (8 col-groups cg) x (16 row-groups rg of 16 bt rows).
// [R13 body]
// =========================================================================
__global__ void __launch_bounds__(256) k4_attn(const float* __restrict__ Wa,
                                               const float* __restrict__ ba,
                                               const float* __restrict__ ua) {
    const int cg = blockIdx.x & 7;        // col group: cols cg*32..+31
    const int rg = blockIdx.x >> 3;       // row group: bt rows rg*16..+15
    const int tid = threadIdx.x;
    const int lane = tid & 31, w = tid >> 5;
    const int col = cg * 32 + lane;
    __shared__ float rows_sm[16][DIN];    // 8KB
    __shared__ float wa_sm[DIN][32];      // 16KB  [k][c]

    // stage 16 lstm_out rows: 512 float4 / 256 threads (2 each)
    {
        const float4* src = (const float4*)&g_lstm_out[rg * 16 * DIN];
        float4* dst = (float4*)rows_sm;
        dst[tid] = src[tid];
        dst[tid + 256] = src[tid + 256];
    }
    // stage Wa column slice [128][32]: 1024 float4 / 256 threads
    {
#pragma unroll
        for (int i = 0; i < 4; i++) {
            const int idx = tid + i * 256;      // float4 index
            const int k = idx >> 3, seg = idx & 7;
            *(float4*)&wa_sm[k][seg * 4] =
                *(const float4*)&Wa[k * AA + cg * 32 + seg * 4];
        }
    }
    __syncthreads();

    // warp w -> local rows w*2, w*2+1; lane -> col
    float acc0 = 0.f, acc1 = 0.f;
    const int r0 = w * 2;
#pragma unroll 4
    for (int kq = 0; kq < 32; kq++) {
        const float4 a0v = *(const float4*)&rows_sm[r0 + 0][kq * 4];
        const float4 a1v = *(const float4*)&rows_sm[r0 + 1][kq * 4];
        const float w0 = wa_sm[kq * 4 + 0][lane];
        const float w1 = wa_sm[kq * 4 + 1][lane];
        const float w2 = wa_sm[kq * 4 + 2][lane];
        const float w3 = wa_sm[kq * 4 + 3][lane];
        acc0 += a0v.x * w0 + a0v.y * w1 + a0v.z * w2 + a0v.w * w3;
        acc1 += a1v.x * w0 + a1v.y * w1 + a1v.z * w2 + a1v.w * w3;
    }
    const float bav = ba[col], uav = ua[col];
    float p0 = tanhf_fast(acc0 + bav) * uav;
    float p1 = tanhf_fast(acc1 + bav) * uav;
#pragma unroll
    for (int o = 16; o > 0; o >>= 1) {
        p0 += __shfl_down_sync(0xffffffffu, p0, o);
        p1 += __shfl_down_sync(0xffffffffu, p1, o);
    }
    if (lane == 0) {
        const int bt = rg * 16 + r0;
        g_epart[cg][bt + 0] = p0;
        g_epart[cg][bt + 1] = p1;
    }
}

// =========================================================================
// K5: sum logit partials, softmax over t, context, leaky_relu, head.
// grid 8 (b), 128 threads. [R13 body]
// =========================================================================
__global__ void __launch_bounds__(128) k5_head(const float* __restrict__ Wo,
                                               const float* __restrict__ bo,
                                               float* __restrict__ out) {
    const int b = blockIdx.x;
    const int tid = threadIdx.x;
    __shared__ float alpha[TT];
    __shared__ float red[128];

    if (tid < 32) {
        float e = 0.f;
#pragma unroll
        for (int cg = 0; cg < 8; cg++) e += g_epart[cg][b * TT + tid];
        float m = e;
#pragma unroll
        for (int o = 16; o > 0; o >>= 1) m = fmaxf(m, __shfl_xor_sync(0xffffffffu, m, o));
        float ex = __expf(e - m);
        float sum = ex;
#pragma unroll
        for (int o = 16; o > 0; o >>= 1) sum += __shfl_xor_sync(0xffffffffu, sum, o);
        alpha[tid] = ex / sum;
    }
    __syncthreads();

    float ctx = 0.f;
#pragma unroll 8
    for (int t = 0; t < TT; t++)
        ctx += alpha[t] * g_lstm_out[(b * TT + t) * DIN + tid];
    const float v = (ctx > 0.f) ? ctx : 0.5f * ctx;
    red[tid] = v * Wo[tid];
    __syncthreads();
#pragma unroll
    for (int s = 64; s > 0; s >>= 1) {
        if (tid < s) red[tid] += red[tid + s];
        __syncthreads();
    }
    if (tid == 0) out[b] = 1.f / (1.f + __expf(-(red[0] + bo[0])));
}

// =========================================================================
extern "C" void kernel_launch(void* const* d_in, const int* in_sizes, int n_in,
                              void* d_out, int out_size) {
    const float* x     = (const float*)d_in[0];
    // d_in[1] = visit_lens (int64) — unused by the reference math
    const float* emb   = (const float*)d_in[2];
    const float* Wg    = (const float*)d_in[3];
    const float* bg    = (const float*)d_in[4];
    const float* Wih_f = (const float*)d_in[5];
    const float* Whh_f = (const float*)d_in[6];
    const float* b_f   = (const float*)d_in[7];
    const float* Wih_b = (const float*)d_in[8];
    const float* Whh_b = (const float*)d_in[9];
    const float* b_b   = (const float*)d_in[10];
    const float* Wa    = (const float*)d_in[11];
    const float* ba    = (const float*)d_in[12];
    const float* ua    = (const float*)d_in[13];
    const float* Wo    = (const float*)d_in[14];
    const float* bo    = (const float*)d_in[15];
    float* out = (float*)d_out;

    k1_codes<<<dim3(TT, CSPLIT), 256>>>(x, emb);
    k2_prep<<<dim3(TT, 2), 256>>>(Wg, bg, Wih_f, b_f, Wih_b, b_b);
    k3_lstm<<<16, 256>>>(Whh_f, Whh_b);
    k4_attn<<<128, 256>>>(Wa, ba, ua);
    k5_head<<<BB, 128>>>(Wo, bo, out);
}

// round 16
// speedup vs baseline: 1.6248x; 1.1525x over previous
#include <cuda_runtime.h>
#include <cstdint>

// Problem constants
#define BB 8
#define TT 32
#define CC 4880
#define DD 64
#define HH 64
#define AA 256
#define NG 256        // 4*H gate width
#define DIN 128       // 2*D
#define CSPLIT 16
#define NCG 16        // k4 column groups

// ---------------- scratch (device globals; no allocation) ----------------
__device__ float g_Spart[CSPLIT][TT][BB][DD];   // partial code sums
__device__ float g_CntPart[CSPLIT][TT][BB];     // partial nonzero counts
__device__ float g_Z[2][BB][TT][NG];            // input projections (dir, b, t, gate)
__device__ float g_lstm_out[BB * TT * 2 * HH];  // [b][t][128]
__device__ float g_epart[NCG][BB * TT];         // attention logit partials

// ---------------- math helpers ----------------
__device__ __forceinline__ float sigf(float x) {
    return 1.0f / (1.0f + __expf(-x));
}
__device__ __forceinline__ float tanhf_fast(float x) {
    return 1.0f - 2.0f / (__expf(2.0f * x) + 1.0f);
}

// =========================================================================
// K1: partial sums S[b,t,d] = sum_c x[b,t,c] * emb[c,d]  + count partials
// grid (32 t, 16 split), 256 threads (8 warps). Body identical to the
// proven R13/R15 shape (spill-free); only the split count doubled for
// more resident blocks per SM.
// =========================================================================
__global__ void __launch_bounds__(256) k1_codes(const float* __restrict__ x,
                                                const float* __restrict__ emb) {
    const int t = blockIdx.x, split = blockIdx.y;
    const int w = threadIdx.x >> 5, lane = threadIdx.x & 31;
    const int d0 = lane * 2;

    float acc[BB][2];
    float csum[BB];
#pragma unroll
    for (int b = 0; b < BB; b++) { acc[b][0] = 0.f; acc[b][1] = 0.f; csum[b] = 0.f; }

#pragma unroll 2
    for (int gi = split; gi * 32 < CC; gi += CSPLIT) {
        const int c0 = gi * 32 + w * 4;
        if (c0 < CC) {
            float2 e2[4];
#pragma unroll
            for (int ccx = 0; ccx < 4; ccx++)
                e2[ccx] = *(const float2*)&emb[(c0 + ccx) * DD + d0];
#pragma unroll
            for (int b = 0; b < BB; b++) {
                const float4 xv = *(const float4*)&x[(size_t)(b * TT + t) * CC + c0];
                acc[b][0] += xv.x * e2[0].x + xv.y * e2[1].x + xv.z * e2[2].x + xv.w * e2[3].x;
                acc[b][1] += xv.x * e2[0].y + xv.y * e2[1].y + xv.z * e2[2].y + xv.w * e2[3].y;
                csum[b] += (xv.x + xv.y) + (xv.z + xv.w);
            }
        }
    }

    __shared__ float2 wp[8][BB][DD / 2];
    __shared__ float cw[8][BB];
#pragma unroll
    for (int b = 0; b < BB; b++)
        wp[w][b][lane] = make_float2(acc[b][0], acc[b][1]);
    if (lane == 0) {
#pragma unroll
        for (int b = 0; b < BB; b++) cw[w][b] = csum[b];
    }
    __syncthreads();

    for (int o = threadIdx.x; o < BB * DD; o += 256) {
        const int b = o >> 6, d = o & 63;
        float s = 0.f;
#pragma unroll
        for (int ww = 0; ww < 8; ww++) {
            const float2 v = wp[ww][b][d >> 1];
            s += (d & 1) ? v.y : v.x;
        }
        g_Spart[split][t][b][d] = s;
    }
    if (threadIdx.x < BB) {
        float s = 0.f;
#pragma unroll
        for (int ww = 0; ww < 8; ww++) s += cw[ww][threadIdx.x];
        g_CntPart[split][t][threadIdx.x] = s;
    }
}

// =========================================================================
// K2: per (t, dir): counts, avg_xt, avg_ht, z projection.
// grid (32 t, 2 dir), 256 threads. [R15 body; partial loops now 16-wide]
// =========================================================================
__global__ void __launch_bounds__(256) k2_prep(const float* __restrict__ Wg,
                                               const float* __restrict__ bg,
                                               const float* __restrict__ Wih_f,
                                               const float* __restrict__ b_f,
                                               const float* __restrict__ Wih_b,
                                               const float* __restrict__ b_b) {
    const int t = blockIdx.x, dir = blockIdx.y;
    const int tid = threadIdx.x;
    __shared__ float rows[BB][DIN];         // 4KB
    __shared__ float4 wbuf2[2][512];        // 16KB: [slot][8 k-rows x 64 quads]
    __shared__ float cnt_sm[BB], has_sm[BB];

    // ---- stage Wg into wbuf2 (1024 float4, 4 each) ----
    {
        const float4* src = (const float4*)Wg;
        float4* dst = (float4*)wbuf2;
#pragma unroll
        for (int i = 0; i < 4; i++) dst[tid + i * 256] = src[tid + i * 256];
    }
    // ---- counts from partials ----
    if (tid < BB) {
        float s = 0.f;
#pragma unroll
        for (int sp = 0; sp < CSPLIT; sp++) s += g_CntPart[sp][t][tid];
        cnt_sm[tid] = fmaxf(s, 1.f);
        has_sm[tid] = (s > 0.f) ? 1.f : 0.f;
    }
    __syncthreads();

    // ---- avg_xt: 512 outputs, 2 per thread ----
#pragma unroll
    for (int r = 0; r < 2; r++) {
        const int o = tid + r * 256;
        const int b = o >> 6, d = o & 63;
        float s = 0.f;
#pragma unroll
        for (int sp = 0; sp < CSPLIT; sp++) s += g_Spart[sp][t][b][d];
        rows[b][DD + d] = s / cnt_sm[b];
    }
    __syncthreads();

    // ---- avg_ht = avg_xt @ Wg + bg*has : 2 outputs per thread ----
#pragma unroll
    for (int r = 0; r < 2; r++) {
        const int o = tid + r * 256;
        const int b = o >> 6, d = o & 63;
        const float* wg_sm = (const float*)wbuf2;
        float a = bg[d] * has_sm[b];
#pragma unroll 16
        for (int k = 0; k < DD; k++) a += rows[b][DD + k] * wg_sm[k * DD + d];
        rows[b][d] = a;
    }
    __syncthreads();

    // ---- z = lstm_in @ Wih + bias : double-buffered chunks ----
    const float* __restrict__ Wih  = dir ? Wih_b : Wih_f;
    const float* __restrict__ bias = dir ? b_b : b_f;
    const int q = tid & 63, bg2 = tid >> 6;   // gate quad, b-pair index
    const int b0 = bg2 * 2;
    const float4 bv = *(const float4*)&bias[q * 4];
    float acc0[4] = {bv.x, bv.y, bv.z, bv.w};
    float acc1[4] = {bv.x, bv.y, bv.z, bv.w};

    // preload chunk 0 (8 k-rows = 512 float4; 2 per thread)
    float4 ra = ((const float4*)Wih)[tid];
    float4 rb = ((const float4*)Wih)[tid + 256];
    {
        float4* ds = &wbuf2[0][0];
        ds[tid] = ra;
        ds[tid + 256] = rb;
    }
    __syncthreads();

    for (int ch = 0; ch < 16; ch++) {
        const int slot = ch & 1;
        if (ch < 15) {
            const float4* wsrc = (const float4*)&Wih[(ch + 1) * 8 * NG];
            ra = wsrc[tid];
            rb = wsrc[tid + 256];
        }
        const float4* cs = &wbuf2[slot][0];
#pragma unroll
        for (int kk = 0; kk < 8; kk++) {
            const float4 wv = cs[kk * 64 + q];
            const int k = ch * 8 + kk;
            const float r0 = rows[b0][k];
            const float r1 = rows[b0 + 1][k];
            acc0[0] += r0 * wv.x; acc0[1] += r0 * wv.y; acc0[2] += r0 * wv.z; acc0[3] += r0 * wv.w;
            acc1[0] += r1 * wv.x; acc1[1] += r1 * wv.y; acc1[2] += r1 * wv.z; acc1[3] += r1 * wv.w;
        }
        if (ch < 15) {
            float4* ds = &wbuf2[slot ^ 1][0];
            ds[tid] = ra;
            ds[tid + 256] = rb;
        }
        __syncthreads();
    }
    *(float4*)&g_Z[dir][b0][t][q * 4]     = make_float4(acc0[0], acc0[1], acc0[2], acc0[3]);
    *(float4*)&g_Z[dir][b0 + 1][t][q * 4] = make_float4(acc1[0], acc1[1], acc1[2], acc1[3]);
}

// =========================================================================
// K3: bidirectional LSTM, split by (dir, batch). grid=16, 256 threads.
// [R10/R15 body]
// =========================================================================
__global__ void __launch_bounds__(256, 1) k3_lstm(const float* __restrict__ Whh_f,
                                                  const float* __restrict__ Whh_b) {
    const int dir = blockIdx.x >> 3;
    const int b = blockIdx.x & 7;
    const float* __restrict__ Whh = dir ? Whh_b : Whh_f;
    __shared__ float h_sm[HH];
    __shared__ float z_sm[NG];
    const int g = threadIdx.x;

    unsigned long long wpk[32];
#pragma unroll
    for (int i = 0; i < 32; i++) {
        const float w0 = Whh[(2 * i) * NG + g];
        const float w1 = Whh[(2 * i + 1) * NG + g];
        asm("mov.b64 %0, {%1, %2};" : "=l"(wpk[i]) : "f"(w0), "f"(w1));
    }
    if (g < HH) h_sm[g] = 0.f;
    float cst = 0.f;
    __syncthreads();

    const float* __restrict__ zrow = &g_Z[dir][b][0][0];
    float* __restrict__ orow = &g_lstm_out[b * TT * (2 * HH) + dir * HH];

    const int t0 = dir ? (TT - 1) : 0;
    float zcur = zrow[t0 * NG + g];

    for (int s = 0; s < TT; s++) {
        const int t = dir ? (TT - 1 - s) : s;
        float znext = 0.f;
        if (s + 1 < TT) {
            const int tn = dir ? (TT - 2 - s) : (s + 1);
            znext = zrow[tn * NG + g];
        }
        unsigned long long a0 = 0ull, a1 = 0ull, a2 = 0ull, a3 = 0ull;
        const ulonglong2* hp = (const ulonglong2*)h_sm;
#pragma unroll
        for (int i = 0; i < 16; i += 2) {
            const ulonglong2 h0 = hp[i];
            const ulonglong2 h1 = hp[i + 1];
            asm("fma.rn.f32x2 %0, %1, %2, %0;" : "+l"(a0) : "l"(wpk[2 * i]),     "l"(h0.x));
            asm("fma.rn.f32x2 %0, %1, %2, %0;" : "+l"(a1) : "l"(wpk[2 * i + 1]), "l"(h0.y));
            asm("fma.rn.f32x2 %0, %1, %2, %0;" : "+l"(a2) : "l"(wpk[2 * i + 2]), "l"(h1.x));
            asm("fma.rn.f32x2 %0, %1, %2, %0;" : "+l"(a3) : "l"(wpk[2 * i + 3]), "l"(h1.y));
        }
        float l0, h0f, l1, h1f, l2, h2f, l3, h3f;
        asm("mov.b64 {%0, %1}, %2;" : "=f"(l0), "=f"(h0f) : "l"(a0));
        asm("mov.b64 {%0, %1}, %2;" : "=f"(l1), "=f"(h1f) : "l"(a1));
        asm("mov.b64 {%0, %1}, %2;" : "=f"(l2), "=f"(h2f) : "l"(a2));
        asm("mov.b64 {%0, %1}, %2;" : "=f"(l3), "=f"(h3f) : "l"(a3));
        z_sm[g] = zcur + ((l0 + h0f) + (l1 + h1f)) + ((l2 + h2f) + (l3 + h3f));
        __syncthreads();

        if (g < HH) {
            const float ziv = z_sm[g];
            const float zfv = z_sm[64 + g];
            const float zgv = z_sm[128 + g];
            const float zov = z_sm[192 + g];
            const float ig = sigf(ziv), fg = sigf(zfv);
            const float gg = tanhf_fast(zgv), og = sigf(zov);
            cst = fg * cst + ig * gg;
            const float hnew = og * tanhf_fast(cst);
            h_sm[g] = hnew;
            orow[t * (2 * HH) + g] = hnew;
        }
        __syncthreads();
        zcur = znext;
    }
}

// =========================================================================
// K4: attention logit partials, 16 col-groups x 16 row-groups.
// grid 256, 256 threads. Block stages Wa[:, cg*16:+15] (8KB) + 16 rows
// (8KB); thread (r, c) computes acc[row rg*16+r, col cg*16+c] fully;
// width-16 shuffle reduce -> g_epart[cg][bt].
// =========================================================================
__global__ void __launch_bounds__(256) k4_attn(const float* __restrict__ Wa,
                                               const float* __restrict__ ba,
                                               const float* __restrict__ ua) {
    const int cg = blockIdx.x & 15;       // col group: cols cg*16..+15
    const int rg = blockIdx.x >> 4;       // row group: bt rows rg*16..+15
    const int tid = threadIdx.x;
    const int c = tid & 15, r = tid >> 4;
    const int col = cg * 16 + c;
    __shared__ float rows_sm[16][DIN];    // 8KB
    __shared__ float wa_sm[DIN][16];      // 8KB  [k][c]

    // stage 16 lstm_out rows: 512 float4 / 256 threads (2 each)
    {
        const float4* src = (const float4*)&g_lstm_out[rg * 16 * DIN];
        float4* dst = (float4*)rows_sm;
        dst[tid] = src[tid];
        dst[tid + 256] = src[tid + 256];
    }
    // stage Wa column slice [128][16]: 512 float4 / 256 threads (2 each)
    {
#pragma unroll
        for (int i = 0; i < 2; i++) {
            const int idx = tid + i * 256;      // float4 index
            const int k = idx >> 2, seg = idx & 3;
            *(float4*)&wa_sm[k][seg * 4] =
                *(const float4*)&Wa[k * AA + cg * 16 + seg * 4];
        }
    }
    __syncthreads();

    float ac0 = 0.f, ac1 = 0.f, ac2 = 0.f, ac3 = 0.f;
#pragma unroll 8
    for (int kq = 0; kq < 32; kq++) {
        const float4 a = *(const float4*)&rows_sm[r][kq * 4];
        ac0 += a.x * wa_sm[kq * 4 + 0][c];
        ac1 += a.y * wa_sm[kq * 4 + 1][c];
        ac2 += a.z * wa_sm[kq * 4 + 2][c];
        ac3 += a.w * wa_sm[kq * 4 + 3][c];
    }
    const float acc = (ac0 + ac1) + (ac2 + ac3);
    float p = tanhf_fast(acc + ba[col]) * ua[col];
    // reduce over the 16 c-lanes (width-16 shuffle)
#pragma unroll
    for (int o = 8; o > 0; o >>= 1)
        p += __shfl_down_sync(0xffffffffu, p, o, 16);
    if (c == 0) g_epart[cg][rg * 16 + r] = p;
}

// =========================================================================
// K5: sum logit partials, softmax over t, context, leaky_relu, head.
// grid 8 (b), 128 threads.
// =========================================================================
__global__ void __launch_bounds__(128) k5_head(const float* __restrict__ Wo,
                                               const float* __restrict__ bo,
                                               float* __restrict__ out) {
    const int b = blockIdx.x;
    const int tid = threadIdx.x;
    __shared__ float alpha[TT];
    __shared__ float red[128];

    if (tid < 32) {
        float e = 0.f;
#pragma unroll
        for (int cg = 0; cg < NCG; cg++) e += g_epart[cg][b * TT + tid];
        float m = e;
#pragma unroll
        for (int o = 16; o > 0; o >>= 1) m = fmaxf(m, __shfl_xor_sync(0xffffffffu, m, o));
        float ex = __expf(e - m);
        float sum = ex;
#pragma unroll
        for (int o = 16; o > 0; o >>= 1) sum += __shfl_xor_sync(0xffffffffu, sum, o);
        alpha[tid] = ex / sum;
    }
    __syncthreads();

    float ctx = 0.f;
#pragma unroll 8
    for (int t = 0; t < TT; t++)
        ctx += alpha[t] * g_lstm_out[(b * TT + t) * DIN + tid];
    const float v = (ctx > 0.f) ? ctx : 0.5f * ctx;
    red[tid] = v * Wo[tid];
    __syncthreads();
#pragma unroll
    for (int s = 64; s > 0; s >>= 1) {
        if (tid < s) red[tid] += red[tid + s];
        __syncthreads();
    }
    if (tid == 0) out[b] = 1.f / (1.f + __expf(-(red[0] + bo[0])));
}

// =========================================================================
extern "C" void kernel_launch(void* const* d_in, const int* in_sizes, int n_in,
                              void* d_out, int out_size) {
    const float* x     = (const float*)d_in[0];
    // d_in[1] = visit_lens (int64) — unused by the reference math
    const float* emb   = (const float*)d_in[2];
    const float* Wg    = (const float*)d_in[3];
    const float* bg    = (const float*)d_in[4];
    const float* Wih_f = (const float*)d_in[5];
    const float* Whh_f = (const float*)d_in[6];
    const float* b_f   = (const float*)d_in[7];
    const float* Wih_b = (const float*)d_in[8];
    const float* Whh_b = (const float*)d_in[9];
    const float* b_b   = (const float*)d_in[10];
    const float* Wa    = (const float*)d_in[11];
    const float* ba    = (const float*)d_in[12];
    const float* ua    = (const float*)d_in[13];
    const float* Wo    = (const float*)d_in[14];
    const float* bo    = (const float*)d_in[15];
    float* out = (float*)d_out;

    k1_codes<<<dim3(TT, CSPLIT), 256>>>(x, emb);
    k2_prep<<<dim3(TT, 2), 256>>>(Wg, bg, Wih_f, b_f, Wih_b, b_b);
    k3_lstm<<<16, 256>>>(Whh_f, Whh_b);
    k4_attn<<<NCG * 16, 256>>>(Wa, ba, ua);
    k5_head<<<BB, 128>>>(Wo, bo, out);
}